// round 6
// baseline (speedup 1.0000x reference)
#include <cuda_runtime.h>
#include <math.h>

// PoseCost: SE(3) log-map pose error over B*H poses.
// Inputs: pos [N,3], rot [N,9], gpos[3], grot[9], wv[6]
// Output (9N floats): [cost(N) | rot_err(N) | pos_err(N) | v(3N) | omega(3N)]
// Strategy: smem-staged float4 loads/stores for the [N,3]/[N,9] arrays so all
// HBM transactions are 16B-vectorized; compute is 1 pose/thread.

#define ROT_ERR_W 15.0f
#define TRANS_ERR_W 100.0f
#define TPB 256

__global__ void __launch_bounds__(TPB) pose_cost_kernel(
    const float* __restrict__ pos,    // [N,3]
    const float* __restrict__ rot,    // [N,9]
    const float* __restrict__ gpos,   // [3]
    const float* __restrict__ grot,   // [9]
    const float* __restrict__ wv,     // [6]
    float* __restrict__ out,          // [9N]
    int N)
{
    __shared__ float sR[TPB * 9];   // rot staging, later reused for v | omega
    __shared__ float sP[TPB * 3];   // pos staging

    const int tid = threadIdx.x;
    const int base = blockIdx.x * TPB;
    const int i = base + tid;

    const bool full = (base + TPB) <= N;

    if (full) {
        // ---- cooperative vectorized staging ----
        // rot: TPB*9 floats = 576 float4 = 2 full rounds of 256 + 64 partial
        const float4* rsrc = (const float4*)(rot + (size_t)base * 9);
        float4* rdst = (float4*)sR;
        rdst[tid] = rsrc[tid];
        rdst[TPB + tid] = rsrc[TPB + tid];
        {
            int k = 2 * TPB + tid;
            if (k < TPB * 9 / 4) rdst[k] = rsrc[k];
        }
        // pos: TPB*3 floats = 192 float4
        const float4* psrc = (const float4*)(pos + (size_t)base * 3);
        float4* pdst = (float4*)sP;
        if (tid < TPB * 3 / 4) pdst[tid] = psrc[tid];
        __syncthreads();
    }

    // ---- broadcast constants (L1-resident) ----
    float G[9];
#pragma unroll
    for (int k = 0; k < 9; k++) G[k] = __ldg(&grot[k]);
    const float g0 = __ldg(&gpos[0]), g1 = __ldg(&gpos[1]), g2 = __ldg(&gpos[2]);
    const float w0r = __ldg(&wv[0]), w1r = __ldg(&wv[1]), w2r = __ldg(&wv[2]);
    const float w0t = __ldg(&wv[3]), w1t = __ldg(&wv[4]), w2t = __ldg(&wv[5]);

    float R[9];
    float p0, p1, p2;
    bool active = i < N;
    if (full) {
        // stride-9 / stride-3 smem reads: conflict-free (coprime with 32)
#pragma unroll
        for (int k = 0; k < 9; k++) R[k] = sR[tid * 9 + k];
        p0 = sP[tid * 3 + 0]; p1 = sP[tid * 3 + 1]; p2 = sP[tid * 3 + 2];
    } else if (active) {
        const float* rp = rot + (size_t)i * 9;
#pragma unroll
        for (int k = 0; k < 9; k++) R[k] = rp[k];
        const float* pp = pos + (size_t)i * 3;
        p0 = pp[0]; p1 = pp[1]; p2 = pp[2];
    }

    float v0 = 0.f, v1 = 0.f, v2 = 0.f, o0 = 0.f, o1 = 0.f, o2 = 0.f;
    float cost = 0.f, rotation_err = 0.f, position_err = 0.f;

    if (active) {
        // ---- R_ge = R^T * G : Rge[a][b] = sum_c R[c*3+a]*G[c*3+b] ----
        float Rge00 = R[0]*G[0] + R[3]*G[3] + R[6]*G[6];
        float Rge01 = R[0]*G[1] + R[3]*G[4] + R[6]*G[7];
        float Rge02 = R[0]*G[2] + R[3]*G[5] + R[6]*G[8];
        float Rge10 = R[1]*G[0] + R[4]*G[3] + R[7]*G[6];
        float Rge11 = R[1]*G[1] + R[4]*G[4] + R[7]*G[7];
        float Rge12 = R[1]*G[2] + R[4]*G[5] + R[7]*G[8];
        float Rge20 = R[2]*G[0] + R[5]*G[3] + R[8]*G[6];
        float Rge21 = R[2]*G[1] + R[5]*G[4] + R[8]*G[7];
        float Rge22 = R[2]*G[2] + R[5]*G[5] + R[8]*G[8];

        // ---- t = R^T * (g - p) ----
        const float d0 = g0 - p0, d1 = g1 - p1, d2 = g2 - p2;
        const float t0 = R[0]*d0 + R[3]*d1 + R[6]*d2;
        const float t1 = R[1]*d0 + R[4]*d1 + R[7]*d2;
        const float t2 = R[2]*d0 + R[5]*d1 + R[8]*d2;

        // ---- SE(3) log ----
        const float tr = Rge00 + Rge11 + Rge22;
        float ct = 0.5f * (tr - 1.0f);
        ct = fminf(fmaxf(ct, -1.0f + 1e-7f), 1.0f - 1e-7f);
        const float th = acosf(ct);
        const float st = sinf(th);

        const float wv0 = 0.5f * (Rge21 - Rge12);
        const float wv1 = 0.5f * (Rge02 - Rge20);
        const float wv2 = 0.5f * (Rge10 - Rge01);

        const bool small = th < 1e-4f;
        const float safe_sin = small ? 1.0f : st;
        const float scale = small ? (1.0f + th * th * (1.0f / 6.0f)) : (th / safe_sin);

        o0 = scale * wv0; o1 = scale * wv1; o2 = scale * wv2;

        const float th2 = small ? 1.0f : th * th;
        const float A = small ? (1.0f / 12.0f)
                              : (1.0f - (th * st) / (2.0f * (1.0f - ct))) / th2;

        // v = (1 - A|o|^2) t - 0.5 (o x t) + A (o.t) o
        const float on2 = o0*o0 + o1*o1 + o2*o2;
        const float odt = o0*t0 + o1*t1 + o2*t2;
        const float c0 = o1*t2 - o2*t1;
        const float c1 = o2*t0 - o0*t2;
        const float c2 = o0*t1 - o1*t0;
        const float k1 = 1.0f - A * on2;
        v0 = k1*t0 - 0.5f*c0 + A*odt*o0;
        v1 = k1*t1 - 0.5f*c1 + A*odt*o1;
        v2 = k1*t2 - 0.5f*c2 + A*odt*o2;

        const float e0 = w0t * v0, e1 = w1t * v1, e2 = w2t * v2;
        position_err = e0*e0 + e1*e1 + e2*e2;
        const float r0 = w0r * o0, r1 = w1r * o1, r2 = w2r * o2;
        rotation_err = r0*r0 + r1*r1 + r2*r2;
        cost = ROT_ERR_W * rotation_err + TRANS_ERR_W * position_err;
    }

    // ---- scalar outputs (contiguous, coalesced) ----
    if (active) {
        out[i] = cost;
        out[(size_t)N + i] = rotation_err;
        out[2 * (size_t)N + i] = position_err;
    }

    if (full) {
        // ---- vectorized v / omega stores via smem (reuse sR) ----
        __syncthreads();  // done reading rot from sR
        float* sv = sR;             // TPB*3
        float* so = sR + TPB * 3;   // TPB*3
        sv[tid * 3 + 0] = v0; sv[tid * 3 + 1] = v1; sv[tid * 3 + 2] = v2;
        so[tid * 3 + 0] = o0; so[tid * 3 + 1] = o1; so[tid * 3 + 2] = o2;
        __syncthreads();
        float4* vdst = (float4*)(out + 3 * (size_t)N + (size_t)base * 3);
        float4* odst = (float4*)(out + 6 * (size_t)N + (size_t)base * 3);
        const float4* vsrc = (const float4*)sv;
        const float4* osrc = (const float4*)so;
        if (tid < TPB * 3 / 4) {
            vdst[tid] = vsrc[tid];
            odst[tid] = osrc[tid];
        }
    } else if (active) {
        float* vout = out + 3 * (size_t)N + (size_t)i * 3;
        vout[0] = v0; vout[1] = v1; vout[2] = v2;
        float* oout = out + 6 * (size_t)N + (size_t)i * 3;
        oout[0] = o0; oout[1] = o1; oout[2] = o2;
    }
}

extern "C" void kernel_launch(void* const* d_in, const int* in_sizes, int n_in,
                              void* d_out, int out_size) {
    const float* pos  = (const float*)d_in[0];
    const float* rot  = (const float*)d_in[1];
    const float* gpos = (const float*)d_in[2];
    const float* grot = (const float*)d_in[3];
    const float* wv   = (const float*)d_in[4];
    float* out = (float*)d_out;

    const int N = in_sizes[0] / 3;  // B*H
    const int blocks = (N + TPB - 1) / TPB;
    pose_cost_kernel<<<blocks, TPB>>>(pos, rot, gpos, grot, wv, out, N);
}

// round 7
// speedup vs baseline: 1.0655x; 1.0655x over previous
#include <cuda_runtime.h>
#include <math.h>

// PoseCost: SE(3) log-map pose error over B*H poses.
// Inputs: pos [N,3], rot [N,9], gpos[3], grot[9], wv[6]
// Output (9N floats): [cost(N) | rot_err(N) | pos_err(N) | v(3N) | omega(3N)]
// R7: direct scalar loads (coalescer merges stride-9 fine), no smem/barriers,
// __launch_bounds__ to cap regs at 40 for ~2x occupancy vs R2, streaming
// cache hints since nothing is re-read.

#define ROT_ERR_W 15.0f
#define TRANS_ERR_W 100.0f
#define TPB 256

__global__ void __launch_bounds__(TPB) pose_cost_kernel(
    const float* __restrict__ pos,    // [N,3]
    const float* __restrict__ rot,    // [N,9]
    const float* __restrict__ gpos,   // [3]
    const float* __restrict__ grot,   // [9]
    const float* __restrict__ wv,     // [6]
    float* __restrict__ out,          // [9N]
    int N)
{
    int i = blockIdx.x * blockDim.x + threadIdx.x;
    if (i >= N) return;

    // ---- per-pose loads first (max MLP, streaming: no reuse) ----
    float R[9];
    const float* rp = rot + (size_t)i * 9;
#pragma unroll
    for (int k = 0; k < 9; k++) R[k] = __ldcs(&rp[k]);
    const float* pp = pos + (size_t)i * 3;
    const float p0 = __ldcs(&pp[0]), p1 = __ldcs(&pp[1]), p2 = __ldcs(&pp[2]);

    // ---- broadcast constants (L1-resident) ----
    float G[9];
#pragma unroll
    for (int k = 0; k < 9; k++) G[k] = __ldg(&grot[k]);
    const float g0 = __ldg(&gpos[0]), g1 = __ldg(&gpos[1]), g2 = __ldg(&gpos[2]);
    const float w0r = __ldg(&wv[0]), w1r = __ldg(&wv[1]), w2r = __ldg(&wv[2]);
    const float w0t = __ldg(&wv[3]), w1t = __ldg(&wv[4]), w2t = __ldg(&wv[5]);

    // ---- R_ge = R^T * G : Rge[a][b] = sum_c R[c*3+a]*G[c*3+b] ----
    float Rge00 = R[0]*G[0] + R[3]*G[3] + R[6]*G[6];
    float Rge01 = R[0]*G[1] + R[3]*G[4] + R[6]*G[7];
    float Rge02 = R[0]*G[2] + R[3]*G[5] + R[6]*G[8];
    float Rge10 = R[1]*G[0] + R[4]*G[3] + R[7]*G[6];
    float Rge11 = R[1]*G[1] + R[4]*G[4] + R[7]*G[7];
    float Rge12 = R[1]*G[2] + R[4]*G[5] + R[7]*G[8];
    float Rge20 = R[2]*G[0] + R[5]*G[3] + R[8]*G[6];
    float Rge21 = R[2]*G[1] + R[5]*G[4] + R[8]*G[7];
    float Rge22 = R[2]*G[2] + R[5]*G[5] + R[8]*G[8];

    // ---- t = R^T * (g - p) ----
    const float d0 = g0 - p0, d1 = g1 - p1, d2 = g2 - p2;
    const float t0 = R[0]*d0 + R[3]*d1 + R[6]*d2;
    const float t1 = R[1]*d0 + R[4]*d1 + R[7]*d2;
    const float t2 = R[2]*d0 + R[5]*d1 + R[8]*d2;

    // ---- SE(3) log ----
    const float tr = Rge00 + Rge11 + Rge22;
    float ct = 0.5f * (tr - 1.0f);
    ct = fminf(fmaxf(ct, -1.0f + 1e-7f), 1.0f - 1e-7f);
    const float th = acosf(ct);
    const float st = sinf(th);

    const float wv0 = 0.5f * (Rge21 - Rge12);
    const float wv1 = 0.5f * (Rge02 - Rge20);
    const float wv2 = 0.5f * (Rge10 - Rge01);

    const bool small = th < 1e-4f;
    const float safe_sin = small ? 1.0f : st;
    const float scale = small ? (1.0f + th * th * (1.0f / 6.0f)) : (th / safe_sin);

    const float o0 = scale * wv0;
    const float o1 = scale * wv1;
    const float o2 = scale * wv2;

    const float th2 = small ? 1.0f : th * th;
    const float A = small ? (1.0f / 12.0f)
                          : (1.0f - (th * st) / (2.0f * (1.0f - ct))) / th2;

    // v = (1 - A|o|^2) t - 0.5 (o x t) + A (o.t) o
    const float on2 = o0*o0 + o1*o1 + o2*o2;
    const float odt = o0*t0 + o1*t1 + o2*t2;
    const float c0 = o1*t2 - o2*t1;
    const float c1 = o2*t0 - o0*t2;
    const float c2 = o0*t1 - o1*t0;
    const float k1 = 1.0f - A * on2;
    const float v0 = k1*t0 - 0.5f*c0 + A*odt*o0;
    const float v1 = k1*t1 - 0.5f*c1 + A*odt*o1;
    const float v2 = k1*t2 - 0.5f*c2 + A*odt*o2;

    // ---- costs ----
    const float e0 = w0t * v0, e1 = w1t * v1, e2 = w2t * v2;
    const float position_err = e0*e0 + e1*e1 + e2*e2;
    const float r0 = w0r * o0, r1 = w1r * o1, r2 = w2r * o2;
    const float rotation_err = r0*r0 + r1*r1 + r2*r2;
    const float cost = ROT_ERR_W * rotation_err + TRANS_ERR_W * position_err;

    // ---- outputs: [cost | rot_err | pos_err | v(3N) | omega(3N)] ----
    __stcs(&out[i], cost);
    __stcs(&out[(size_t)N + i], rotation_err);
    __stcs(&out[2 * (size_t)N + i], position_err);
    float* vout = out + 3 * (size_t)N + (size_t)i * 3;
    __stcs(&vout[0], v0); __stcs(&vout[1], v1); __stcs(&vout[2], v2);
    float* oout = out + 6 * (size_t)N + (size_t)i * 3;
    __stcs(&oout[0], o0); __stcs(&oout[1], o1); __stcs(&oout[2], o2);
}

extern "C" void kernel_launch(void* const* d_in, const int* in_sizes, int n_in,
                              void* d_out, int out_size) {
    const float* pos  = (const float*)d_in[0];
    const float* rot  = (const float*)d_in[1];
    const float* gpos = (const float*)d_in[2];
    const float* grot = (const float*)d_in[3];
    const float* wv   = (const float*)d_in[4];
    float* out = (float*)d_out;

    const int N = in_sizes[0] / 3;  // B*H
    const int blocks = (N + TPB - 1) / TPB;
    pose_cost_kernel<<<blocks, TPB>>>(pos, rot, gpos, grot, wv, out, N);
}